// round 9
// baseline (speedup 1.0000x reference)
#include <cuda_runtime.h>
#include <cuda_fp16.h>
#include <mma.h>
#include <stdint.h>

using namespace nvcuda;

#define MAXN 100000
#define MAXE 1600000
#define HID  64
#define CAP  128   // max in-degree capacity, multiple of 16

// ---------------- device scratch (zero-initialized at module load) ----------------
static __device__ __align__(256) int    g_cnt[MAXN];                      // 0 at entry; re-zeroed by k_agg2
static __device__ __align__(256) int    g_slot[(size_t)MAXN * CAP];       // bucketed source lists
static __device__ __align__(256) float  g_dinv[MAXN];
static __device__ __align__(256) __half g_hs[(size_t)(MAXN + 1) * HID];   // +1 dummy zero row (id MAXN)
static __device__ __align__(256) float  g_a[(size_t)MAXN * HID];          // layer-1 activations (fp32)

// ---------------- bucket fill: one pass, count + insert ----------------
__global__ void k_fill(const int* __restrict__ src, const int* __restrict__ dst, int e) {
    int base = (blockIdx.x * blockDim.x + threadIdx.x) << 2;
    if (base >= e) return;
    if (base + 4 <= e) {
        int4 d4 = *(const int4*)(dst + base);
        int4 s4 = *(const int4*)(src + base);
        int p0 = atomicAdd(&g_cnt[d4.x], 1);
        int p1 = atomicAdd(&g_cnt[d4.y], 1);
        int p2 = atomicAdd(&g_cnt[d4.z], 1);
        int p3 = atomicAdd(&g_cnt[d4.w], 1);
        if (p0 < CAP) g_slot[(size_t)d4.x * CAP + p0] = s4.x;
        if (p1 < CAP) g_slot[(size_t)d4.y * CAP + p1] = s4.y;
        if (p2 < CAP) g_slot[(size_t)d4.z * CAP + p2] = s4.z;
        if (p3 < CAP) g_slot[(size_t)d4.w * CAP + p3] = s4.w;
    } else {
        for (int i = base; i < e; ++i) {
            int d = dst[i];
            int p = atomicAdd(&g_cnt[d], 1);
            if (p < CAP) g_slot[(size_t)d * CAP + p] = src[i];
        }
    }
}

// ---------------- dinv + pad slot lists to multiple of 16 with dummy id ----------------
__global__ void k_dinv_pad(int n) {
    int i = blockIdx.x * blockDim.x + threadIdx.x;
    if (i >= n) return;
    int dg = min(g_cnt[i], CAP);
    g_dinv[i] = rsqrtf((float)g_cnt[i] + 1.0f);   // +1 self loop (true degree for norm)
    int dg16 = (dg + 15) & ~15;
    int* row = g_slot + (size_t)i * CAP;
    for (int p = dg; p < dg16; ++p) row[p] = MAXN;   // dummy: hs row MAXN is always zero
}

// ---------------- wmma GEMM: hs = half( dinv[row] * (X[n,K] @ W[K,64]) ), single-shot ----------------
#define GEMM_SMEM 53248
__global__ void k_gemm_f16(const float* __restrict__ X, const float* __restrict__ W,
                           __half* __restrict__ Y, int n, int K) {
    extern __shared__ __align__(16) unsigned char smbuf[];
    __half (*sA)[136]  = (__half(*)[136])smbuf;                 // 34816 B
    __half (*sB)[72]   = (__half(*)[72])(smbuf + 34816);        // 18432 B
    float  (*sOut)[68] = (float(*)[68])smbuf;                   // aliases sA after compute

    const int tid = threadIdx.x;
    const int wid = tid >> 5;
    const int wr = wid >> 1;
    const int wc = wid & 1;
    const int rowBase = blockIdx.x * 128;
    const int kq = K >> 2;

    for (int i = tid; i < (128 * K) >> 2; i += 256) {
        int r = i / kq, q = i % kq;
        int row = rowBase + r;
        float4 v = make_float4(0.f, 0.f, 0.f, 0.f);
        if (row < n)
            v = *(const float4*)(X + (size_t)row * K + (q << 2));
        *(__half2*)&sA[r][(q << 2)]     = __floats2half2_rn(v.x, v.y);
        *(__half2*)&sA[r][(q << 2) + 2] = __floats2half2_rn(v.z, v.w);
    }
    for (int i = tid; i < K * 16; i += 256) {
        int r = i >> 4, q = i & 15;
        float4 v = *(const float4*)(W + (size_t)r * 64 + (q << 2));
        *(__half2*)&sB[r][(q << 2)]     = __floats2half2_rn(v.x, v.y);
        *(__half2*)&sB[r][(q << 2) + 2] = __floats2half2_rn(v.z, v.w);
    }
    __syncthreads();

    wmma::fragment<wmma::accumulator, 16, 16, 16, float> acc[2][2];
#pragma unroll
    for (int i = 0; i < 2; ++i)
#pragma unroll
        for (int j = 0; j < 2; ++j) wmma::fill_fragment(acc[i][j], 0.0f);

#pragma unroll
    for (int kk = 0; kk < 128; kk += 16) {
        if (kk >= K) break;
        wmma::fragment<wmma::matrix_a, 16, 16, 16, __half, wmma::row_major> a0, a1;
        wmma::fragment<wmma::matrix_b, 16, 16, 16, __half, wmma::row_major> b0, b1;
        wmma::load_matrix_sync(a0, &sA[wr * 32][kk], 136);
        wmma::load_matrix_sync(a1, &sA[wr * 32 + 16][kk], 136);
        wmma::load_matrix_sync(b0, &sB[kk][wc * 32], 72);
        wmma::load_matrix_sync(b1, &sB[kk][wc * 32 + 16], 72);
        wmma::mma_sync(acc[0][0], a0, b0, acc[0][0]);
        wmma::mma_sync(acc[0][1], a0, b1, acc[0][1]);
        wmma::mma_sync(acc[1][0], a1, b0, acc[1][0]);
        wmma::mma_sync(acc[1][1], a1, b1, acc[1][1]);
    }
    __syncthreads();

#pragma unroll
    for (int i = 0; i < 2; ++i)
#pragma unroll
        for (int j = 0; j < 2; ++j)
            wmma::store_matrix_sync(&sOut[wr * 32 + i * 16][wc * 32 + j * 16],
                                    acc[i][j], 68, wmma::mem_row_major);
    __syncthreads();

    {
        int r = tid >> 1;
        int cb = (tid & 1) << 5;
        int row = rowBase + r;
        if (row < n) {
            float s = g_dinv[row];
#pragma unroll
            for (int jj = 0; jj < 4; ++jj) {
                float4 v0 = *(float4*)&sOut[r][cb + (jj << 3)];
                float4 v1 = *(float4*)&sOut[r][cb + (jj << 3) + 4];
                __half2 h[4];
                h[0] = __floats2half2_rn(v0.x * s, v0.y * s);
                h[1] = __floats2half2_rn(v0.z * s, v0.w * s);
                h[2] = __floats2half2_rn(v1.x * s, v1.y * s);
                h[3] = __floats2half2_rn(v1.z * s, v1.w * s);
                *(uint4*)(Y + (size_t)row * 64 + cb + (jj << 3)) = *(uint4*)h;
            }
        }
    }
}

// ---------------- aggregation core ----------------
// warp layout: q = lane>>3 owns a CONTIGUOUS quarter of the (16-padded) source list,
// r = lane&7 owns channel octet r*8..r*8+7 (16 bytes of the fp16 row).
// Inner loop: 4 sources per iteration, HADD2 pairwise accumulate (<=4 chained half adds),
// flushed to fp32 each iteration. Branch-free (lists padded with dummy zero row).
__device__ __forceinline__ void agg_core(const __half* __restrict__ hs,
                                         int w, int q, int r,
                                         float acc[8]) {
#pragma unroll
    for (int k = 0; k < 8; ++k) acc[k] = 0.f;

    const __half* base = hs + (r << 3);
    if (q == 0) {   // self term, fp32, counted once
        uint4 hv = *(const uint4*)(base + (size_t)w * 64);
        __half2* h2 = (__half2*)&hv;
#pragma unroll
        for (int k = 0; k < 4; ++k) {
            float2 f = __half22float2(h2[k]);
            acc[2 * k] += f.x; acc[2 * k + 1] += f.y;
        }
    }

    int dg   = min(g_cnt[w], CAP);
    int seg  = ((dg + 15) & ~15) >> 2;           // per-quarter count, multiple of 4
    const int* sp = g_slot + (size_t)w * CAP + q * seg;

    for (int t = 0; t < seg; t += 4) {
        int2 s01 = *(const int2*)(sp + t);
        int2 s23 = *(const int2*)(sp + t + 2);
        uint4 v0 = *(const uint4*)(base + (size_t)s01.x * 64);
        uint4 v1 = *(const uint4*)(base + (size_t)s01.y * 64);
        uint4 v2 = *(const uint4*)(base + (size_t)s23.x * 64);
        uint4 v3 = *(const uint4*)(base + (size_t)s23.y * 64);
        __half2* h0 = (__half2*)&v0;
        __half2* h1 = (__half2*)&v1;
        __half2* h2 = (__half2*)&v2;
        __half2* h3 = (__half2*)&v3;
#pragma unroll
        for (int k = 0; k < 4; ++k) {
            __half2 s = __hadd2(__hadd2(h0[k], h1[k]), __hadd2(h2[k], h3[k]));
            float2 f = __half22float2(s);
            acc[2 * k] += f.x; acc[2 * k + 1] += f.y;
        }
    }
    // reduce across the 4 quarter-warps
#pragma unroll
    for (int k = 0; k < 8; ++k) {
        acc[k] += __shfl_xor_sync(0xffffffffu, acc[k], 8);
        acc[k] += __shfl_xor_sync(0xffffffffu, acc[k], 16);
    }
}

// ---------------- layer 1: a[d] = relu(dinv[d]*(hs[d]+sum hs[s]) + b1) ----------------
__global__ void k_agg1(const __half* __restrict__ hs, float* __restrict__ a,
                       const float* __restrict__ b1, int n) {
    int w = (blockIdx.x * blockDim.x + threadIdx.x) >> 5;
    if (w >= n) return;
    int lane = threadIdx.x & 31;
    int q = lane >> 3, r = lane & 7;

    float acc[8];
    agg_core(hs, w, q, r, acc);

    if (q == 0) {
        float dvw = g_dinv[w];
        float4 b0 = *(const float4*)(b1 + (r << 3));
        float4 b1v = *(const float4*)(b1 + (r << 3) + 4);
        float4 o0, o1;
        o0.x = fmaxf(acc[0] * dvw + b0.x, 0.f);
        o0.y = fmaxf(acc[1] * dvw + b0.y, 0.f);
        o0.z = fmaxf(acc[2] * dvw + b0.z, 0.f);
        o0.w = fmaxf(acc[3] * dvw + b0.w, 0.f);
        o1.x = fmaxf(acc[4] * dvw + b1v.x, 0.f);
        o1.y = fmaxf(acc[5] * dvw + b1v.y, 0.f);
        o1.z = fmaxf(acc[6] * dvw + b1v.z, 0.f);
        o1.w = fmaxf(acc[7] * dvw + b1v.w, 0.f);
        *(float4*)(a + (size_t)w * 64 + (r << 3))     = o0;
        *(float4*)(a + (size_t)w * 64 + (r << 3) + 4) = o1;
    }
}

// ---------------- layer 2 + classifier; also re-zeroes g_cnt ----------------
__global__ void k_agg2(const __half* __restrict__ hs,
                       const float* __restrict__ b2, const float* __restrict__ Wc,
                       const float* __restrict__ bc, float* __restrict__ logits, int n) {
    int w = (blockIdx.x * blockDim.x + threadIdx.x) >> 5;
    if (w >= n) return;
    int lane = threadIdx.x & 31;
    int q = lane >> 3, r = lane & 7;

    float acc[8];
    agg_core(hs, w, q, r, acc);

    float dvw = g_dinv[w];
    float4 b0 = *(const float4*)(b2 + (r << 3));
    float4 b1v = *(const float4*)(b2 + (r << 3) + 4);
    float4 wc0 = *(const float4*)(Wc + (r << 3));
    float4 wc1 = *(const float4*)(Wc + (r << 3) + 4);
    float sum =
        fmaxf(acc[0] * dvw + b0.x, 0.f) * wc0.x +
        fmaxf(acc[1] * dvw + b0.y, 0.f) * wc0.y +
        fmaxf(acc[2] * dvw + b0.z, 0.f) * wc0.z +
        fmaxf(acc[3] * dvw + b0.w, 0.f) * wc0.w +
        fmaxf(acc[4] * dvw + b1v.x, 0.f) * wc1.x +
        fmaxf(acc[5] * dvw + b1v.y, 0.f) * wc1.y +
        fmaxf(acc[6] * dvw + b1v.z, 0.f) * wc1.z +
        fmaxf(acc[7] * dvw + b1v.w, 0.f) * wc1.w;
    sum += __shfl_xor_sync(0xffffffffu, sum, 1);
    sum += __shfl_xor_sync(0xffffffffu, sum, 2);
    sum += __shfl_xor_sync(0xffffffffu, sum, 4);
    if (lane == 0) {
        logits[w] = sum + bc[0];
        g_cnt[w] = 0;          // ready for next call (replay determinism)
    }
}

// ---------------- launcher ----------------
extern "C" void kernel_launch(void* const* d_in, const int* in_sizes, int n_in,
                              void* d_out, int out_size) {
    const float* x  = (const float*)d_in[0];
    const int*   ei = (const int*)d_in[1];   // int32 (JAX x64 disabled)
    const float* W1 = (const float*)d_in[2];
    const float* b1 = (const float*)d_in[3];
    const float* W2 = (const float*)d_in[4];
    const float* b2 = (const float*)d_in[5];
    const float* Wc = (const float*)d_in[6];
    const float* bc = (const float*)d_in[7];
    float* logits = (float*)d_out;

    const int n = in_sizes[0] / 128;
    const int e = in_sizes[1] / 2;
    const int* src = ei;
    const int* dst = ei + e;

    __half* p_hs;
    float*  p_a;
    cudaGetSymbolAddress((void**)&p_hs, g_hs);
    cudaGetSymbolAddress((void**)&p_a,  g_a);

    static bool attr_done = false;
    if (!attr_done) {
        cudaFuncSetAttribute(k_gemm_f16, cudaFuncAttributeMaxDynamicSharedMemorySize, GEMM_SMEM);
        attr_done = true;
    }

    const int T = 256;

    // 1: bucket fill (count + insert in one atomic pass)
    k_fill<<<((e >> 2) + T - 1) / T, T>>>(src, dst, e);
    // 2: norms + list padding
    k_dinv_pad<<<(n + T - 1) / T, T>>>(n);
    // 3: layer-1 GEMM
    k_gemm_f16<<<(n + 127) / 128, T, GEMM_SMEM>>>(x, W1, p_hs, n, 128);
    // 4: layer-1 aggregation  (profiled launch — A/B vs R7 37.7us / R8 46.5us)
    k_agg1<<<(n * 32 + T - 1) / T, T>>>(p_hs, p_a, b1, n);
    // 5-6: layer-2 GEMM + aggregation/classifier
    k_gemm_f16<<<(n + 127) / 128, T, GEMM_SMEM>>>(p_a, W2, p_hs, n, 64);
    k_agg2<<<(n * 32 + T - 1) / T, T>>>(p_hs, b2, Wc, bc, logits, n);
}

// round 10
// speedup vs baseline: 1.2480x; 1.2480x over previous
#include <cuda_runtime.h>
#include <cuda_fp16.h>
#include <mma.h>
#include <stdint.h>

using namespace nvcuda;

#define MAXN 100000
#define MAXE 1600000
#define HID  64
#define CAP  128   // max in-degree capacity (Poisson(16): P(deg>=128) ~ 0)

// ---------------- device scratch (zero-initialized at module load) ----------------
static __device__ __align__(256) int    g_cnt[MAXN];                    // 0 at entry; re-zeroed by k_agg2
static __device__ __align__(256) int    g_slot[(size_t)MAXN * CAP];     // bucketed source lists
static __device__ __align__(256) float  g_dinv[MAXN];
static __device__ __align__(256) float  g_hs[(size_t)MAXN * HID];       // dinv-scaled GEMM output (fp32)
static __device__ __align__(256) float  g_a[(size_t)MAXN * HID];        // layer-1 activations (fp32)

// ---------------- bucket fill: one pass, count + insert ----------------
__global__ void k_fill(const int* __restrict__ src, const int* __restrict__ dst, int e) {
    int base = (blockIdx.x * blockDim.x + threadIdx.x) << 2;
    if (base >= e) return;
    if (base + 4 <= e) {
        int4 d4 = *(const int4*)(dst + base);
        int4 s4 = *(const int4*)(src + base);
        int p0 = atomicAdd(&g_cnt[d4.x], 1);
        int p1 = atomicAdd(&g_cnt[d4.y], 1);
        int p2 = atomicAdd(&g_cnt[d4.z], 1);
        int p3 = atomicAdd(&g_cnt[d4.w], 1);
        if (p0 < CAP) g_slot[(size_t)d4.x * CAP + p0] = s4.x;
        if (p1 < CAP) g_slot[(size_t)d4.y * CAP + p1] = s4.y;
        if (p2 < CAP) g_slot[(size_t)d4.z * CAP + p2] = s4.z;
        if (p3 < CAP) g_slot[(size_t)d4.w * CAP + p3] = s4.w;
    } else {
        for (int i = base; i < e; ++i) {
            int d = dst[i];
            int p = atomicAdd(&g_cnt[d], 1);
            if (p < CAP) g_slot[(size_t)d * CAP + p] = src[i];
        }
    }
}

__global__ void k_dinv(int n) {
    int i = blockIdx.x * blockDim.x + threadIdx.x;
    if (i < n) g_dinv[i] = rsqrtf((float)g_cnt[i] + 1.0f);   // +1 self loop
}

// ---------------- wmma GEMM: hs = dinv[row] * (X[n,K] @ W[K,64]), fp32 out, single-shot ----------------
#define GEMM_SMEM 53248
__global__ void k_gemm_f16(const float* __restrict__ X, const float* __restrict__ W,
                           float* __restrict__ Y, int n, int K) {
    extern __shared__ __align__(16) unsigned char smbuf[];
    __half (*sA)[136]  = (__half(*)[136])smbuf;                 // 34816 B
    __half (*sB)[72]   = (__half(*)[72])(smbuf + 34816);        // 18432 B
    float  (*sOut)[68] = (float(*)[68])smbuf;                   // aliases sA after compute

    const int tid = threadIdx.x;
    const int wid = tid >> 5;
    const int wr = wid >> 1;
    const int wc = wid & 1;
    const int rowBase = blockIdx.x * 128;
    const int kq = K >> 2;

    for (int i = tid; i < (128 * K) >> 2; i += 256) {
        int r = i / kq, q = i % kq;
        int row = rowBase + r;
        float4 v = make_float4(0.f, 0.f, 0.f, 0.f);
        if (row < n)
            v = *(const float4*)(X + (size_t)row * K + (q << 2));
        *(__half2*)&sA[r][(q << 2)]     = __floats2half2_rn(v.x, v.y);
        *(__half2*)&sA[r][(q << 2) + 2] = __floats2half2_rn(v.z, v.w);
    }
    for (int i = tid; i < K * 16; i += 256) {
        int r = i >> 4, q = i & 15;
        float4 v = *(const float4*)(W + (size_t)r * 64 + (q << 2));
        *(__half2*)&sB[r][(q << 2)]     = __floats2half2_rn(v.x, v.y);
        *(__half2*)&sB[r][(q << 2) + 2] = __floats2half2_rn(v.z, v.w);
    }
    __syncthreads();

    wmma::fragment<wmma::accumulator, 16, 16, 16, float> acc[2][2];
#pragma unroll
    for (int i = 0; i < 2; ++i)
#pragma unroll
        for (int j = 0; j < 2; ++j) wmma::fill_fragment(acc[i][j], 0.0f);

#pragma unroll
    for (int kk = 0; kk < 128; kk += 16) {
        if (kk >= K) break;
        wmma::fragment<wmma::matrix_a, 16, 16, 16, __half, wmma::row_major> a0, a1;
        wmma::fragment<wmma::matrix_b, 16, 16, 16, __half, wmma::row_major> b0, b1;
        wmma::load_matrix_sync(a0, &sA[wr * 32][kk], 136);
        wmma::load_matrix_sync(a1, &sA[wr * 32 + 16][kk], 136);
        wmma::load_matrix_sync(b0, &sB[kk][wc * 32], 72);
        wmma::load_matrix_sync(b1, &sB[kk][wc * 32 + 16], 72);
        wmma::mma_sync(acc[0][0], a0, b0, acc[0][0]);
        wmma::mma_sync(acc[0][1], a0, b1, acc[0][1]);
        wmma::mma_sync(acc[1][0], a1, b0, acc[1][0]);
        wmma::mma_sync(acc[1][1], a1, b1, acc[1][1]);
    }
    __syncthreads();

#pragma unroll
    for (int i = 0; i < 2; ++i)
#pragma unroll
        for (int j = 0; j < 2; ++j)
            wmma::store_matrix_sync(&sOut[wr * 32 + i * 16][wc * 32 + j * 16],
                                    acc[i][j], 68, wmma::mem_row_major);
    __syncthreads();

    // epilogue: scale by dinv[row], fp32 store; 2 threads per row, 32 cols each
    {
        int r = tid >> 1;
        int cb = (tid & 1) << 5;
        int row = rowBase + r;
        if (row < n) {
            float s = g_dinv[row];
#pragma unroll
            for (int jj = 0; jj < 8; ++jj) {
                float4 v = *(float4*)&sOut[r][cb + (jj << 2)];
                v.x *= s; v.y *= s; v.z *= s; v.w *= s;
                *(float4*)(Y + (size_t)row * 64 + cb + (jj << 2)) = v;
            }
        }
    }
}

// ---------------- aggregation core (R7 shape, fp32 messages) ----------------
// warp layout: q = lane>>3 (source slot within 4-group), r = lane&7 (channel octet).
// Per lane per source: 2 independent LDG.128 + 8 FADD (no conversions).
__device__ __forceinline__ void agg_core(const float* __restrict__ hs,
                                         int w, int q, int r,
                                         float acc[8]) {
    const float* base = hs + (r << 3);
    {   // self term (all quarters load it; divide by 4 at reduce? No—only q==0 adds)
        float4 v0 = make_float4(0.f, 0.f, 0.f, 0.f), v1 = v0;
        if (q == 0) {
            v0 = *(const float4*)(base + (size_t)w * 64);
            v1 = *(const float4*)(base + (size_t)w * 64 + 4);
        }
        acc[0] = v0.x; acc[1] = v0.y; acc[2] = v0.z; acc[3] = v0.w;
        acc[4] = v1.x; acc[5] = v1.y; acc[6] = v1.z; acc[7] = v1.w;
    }

    const int deg = g_cnt[w];
    const int* slotrow = g_slot + (size_t)w * CAP;
    for (int t = 0; t < deg; t += 4) {
        int idx = t + q;
        if (idx < deg) {
            int s = slotrow[idx];
            const float* row = base + (size_t)s * 64;
            float4 v0 = *(const float4*)(row);
            float4 v1 = *(const float4*)(row + 4);
            acc[0] += v0.x; acc[1] += v0.y; acc[2] += v0.z; acc[3] += v0.w;
            acc[4] += v1.x; acc[5] += v1.y; acc[6] += v1.z; acc[7] += v1.w;
        }
    }
    // reduce across the 4 quarter-warps
#pragma unroll
    for (int k = 0; k < 8; ++k) {
        acc[k] += __shfl_xor_sync(0xffffffffu, acc[k], 8);
        acc[k] += __shfl_xor_sync(0xffffffffu, acc[k], 16);
    }
}

// ---------------- layer 1: a[d] = relu(dinv[d]*(hs[d]+sum hs[s]) + b1) ----------------
__global__ void k_agg1(const float* __restrict__ hs, float* __restrict__ a,
                       const float* __restrict__ b1, int n) {
    int w = (blockIdx.x * blockDim.x + threadIdx.x) >> 5;
    if (w >= n) return;
    int lane = threadIdx.x & 31;
    int q = lane >> 3, r = lane & 7;

    float acc[8];
    agg_core(hs, w, q, r, acc);

    if (q == 0) {
        float dvw = g_dinv[w];
        float4 b0 = *(const float4*)(b1 + (r << 3));
        float4 b1v = *(const float4*)(b1 + (r << 3) + 4);
        float4 o0, o1;
        o0.x = fmaxf(acc[0] * dvw + b0.x, 0.f);
        o0.y = fmaxf(acc[1] * dvw + b0.y, 0.f);
        o0.z = fmaxf(acc[2] * dvw + b0.z, 0.f);
        o0.w = fmaxf(acc[3] * dvw + b0.w, 0.f);
        o1.x = fmaxf(acc[4] * dvw + b1v.x, 0.f);
        o1.y = fmaxf(acc[5] * dvw + b1v.y, 0.f);
        o1.z = fmaxf(acc[6] * dvw + b1v.z, 0.f);
        o1.w = fmaxf(acc[7] * dvw + b1v.w, 0.f);
        *(float4*)(a + (size_t)w * 64 + (r << 3))     = o0;
        *(float4*)(a + (size_t)w * 64 + (r << 3) + 4) = o1;
    }
}

// ---------------- layer 2 + classifier; also re-zeroes g_cnt ----------------
__global__ void k_agg2(const float* __restrict__ hs,
                       const float* __restrict__ b2, const float* __restrict__ Wc,
                       const float* __restrict__ bc, float* __restrict__ logits, int n) {
    int w = (blockIdx.x * blockDim.x + threadIdx.x) >> 5;
    if (w >= n) return;
    int lane = threadIdx.x & 31;
    int q = lane >> 3, r = lane & 7;

    float acc[8];
    agg_core(hs, w, q, r, acc);

    float dvw = g_dinv[w];
    float4 b0 = *(const float4*)(b2 + (r << 3));
    float4 b1v = *(const float4*)(b2 + (r << 3) + 4);
    float4 wc0 = *(const float4*)(Wc + (r << 3));
    float4 wc1 = *(const float4*)(Wc + (r << 3) + 4);
    float sum =
        fmaxf(acc[0] * dvw + b0.x, 0.f) * wc0.x +
        fmaxf(acc[1] * dvw + b0.y, 0.f) * wc0.y +
        fmaxf(acc[2] * dvw + b0.z, 0.f) * wc0.z +
        fmaxf(acc[3] * dvw + b0.w, 0.f) * wc0.w +
        fmaxf(acc[4] * dvw + b1v.x, 0.f) * wc1.x +
        fmaxf(acc[5] * dvw + b1v.y, 0.f) * wc1.y +
        fmaxf(acc[6] * dvw + b1v.z, 0.f) * wc1.z +
        fmaxf(acc[7] * dvw + b1v.w, 0.f) * wc1.w;
    sum += __shfl_xor_sync(0xffffffffu, sum, 1);
    sum += __shfl_xor_sync(0xffffffffu, sum, 2);
    sum += __shfl_xor_sync(0xffffffffu, sum, 4);
    if (lane == 0) {
        logits[w] = sum + bc[0];
        g_cnt[w] = 0;          // ready for next call (replay determinism)
    }
}

// ---------------- launcher ----------------
extern "C" void kernel_launch(void* const* d_in, const int* in_sizes, int n_in,
                              void* d_out, int out_size) {
    const float* x  = (const float*)d_in[0];
    const int*   ei = (const int*)d_in[1];   // int32 (JAX x64 disabled)
    const float* W1 = (const float*)d_in[2];
    const float* b1 = (const float*)d_in[3];
    const float* W2 = (const float*)d_in[4];
    const float* b2 = (const float*)d_in[5];
    const float* Wc = (const float*)d_in[6];
    const float* bc = (const float*)d_in[7];
    float* logits = (float*)d_out;

    const int n = in_sizes[0] / 128;
    const int e = in_sizes[1] / 2;
    const int* src = ei;
    const int* dst = ei + e;

    float *p_hs, *p_a;
    cudaGetSymbolAddress((void**)&p_hs, g_hs);
    cudaGetSymbolAddress((void**)&p_a,  g_a);

    static bool attr_done = false;
    if (!attr_done) {
        cudaFuncSetAttribute(k_gemm_f16, cudaFuncAttributeMaxDynamicSharedMemorySize, GEMM_SMEM);
        attr_done = true;
    }

    const int T = 256;

    // 1: bucket fill (count + insert in one atomic pass)
    k_fill<<<((e >> 2) + T - 1) / T, T>>>(src, dst, e);
    // 2: norms
    k_dinv<<<(n + T - 1) / T, T>>>(n);
    // 3: layer-1 GEMM
    k_gemm_f16<<<(n + 127) / 128, T, GEMM_SMEM>>>(x, W1, p_hs, n, 128);
    // 4: layer-1 aggregation  (profiled — A/B: R7 37.7 fp16 / R8 46.5 / R9 63.0 / R10 fp32)
    k_agg1<<<(n * 32 + T - 1) / T, T>>>(p_hs, p_a, b1, n);
    // 5-6: layer-2 GEMM + aggregation/classifier
    k_gemm_f16<<<(n + 127) / 128, T, GEMM_SMEM>>>(p_a, W2, p_hs, n, 64);
    k_agg2<<<(n * 32 + T - 1) / T, T>>>(p_hs, b2, Wc, bc, logits, n);
}

// round 11
// speedup vs baseline: 1.5940x; 1.2773x over previous
#include <cuda_runtime.h>
#include <cuda_fp16.h>
#include <mma.h>
#include <stdint.h>

using namespace nvcuda;

#define MAXN 100000
#define MAXE 1600000
#define HID  64
#define CAP  128   // max in-degree capacity (Poisson(16): P(deg>=128) ~ 0)

// ---------------- device scratch (zero-initialized at module load) ----------------
static __device__ __align__(256) int    g_cnt[MAXN];                    // 0 at entry; re-zeroed by k_agg2
static __device__ __align__(256) int    g_slot[(size_t)MAXN * CAP];     // bucketed source lists
static __device__ __align__(256) __half g_hs[(size_t)MAXN * HID];       // dinv-scaled GEMM output (fp16)
static __device__ __align__(256) float  g_a[(size_t)MAXN * HID];        // layer-1 activations (fp32)

// ---------------- bucket fill: one pass, count + insert, 8 edges per thread (MLP=8) ----------------
__global__ void k_fill(const int* __restrict__ src, const int* __restrict__ dst, int e) {
    int base = (blockIdx.x * blockDim.x + threadIdx.x) << 3;
    if (base >= e) return;
    if (base + 8 <= e) {
        int4 da = *(const int4*)(dst + base);
        int4 db = *(const int4*)(dst + base + 4);
        int4 sa = *(const int4*)(src + base);
        int4 sb = *(const int4*)(src + base + 4);
        int p0 = atomicAdd(&g_cnt[da.x], 1);
        int p1 = atomicAdd(&g_cnt[da.y], 1);
        int p2 = atomicAdd(&g_cnt[da.z], 1);
        int p3 = atomicAdd(&g_cnt[da.w], 1);
        int p4 = atomicAdd(&g_cnt[db.x], 1);
        int p5 = atomicAdd(&g_cnt[db.y], 1);
        int p6 = atomicAdd(&g_cnt[db.z], 1);
        int p7 = atomicAdd(&g_cnt[db.w], 1);
        if (p0 < CAP) g_slot[(size_t)da.x * CAP + p0] = sa.x;
        if (p1 < CAP) g_slot[(size_t)da.y * CAP + p1] = sa.y;
        if (p2 < CAP) g_slot[(size_t)da.z * CAP + p2] = sa.z;
        if (p3 < CAP) g_slot[(size_t)da.w * CAP + p3] = sa.w;
        if (p4 < CAP) g_slot[(size_t)db.x * CAP + p4] = sb.x;
        if (p5 < CAP) g_slot[(size_t)db.y * CAP + p5] = sb.y;
        if (p6 < CAP) g_slot[(size_t)db.z * CAP + p6] = sb.z;
        if (p7 < CAP) g_slot[(size_t)db.w * CAP + p7] = sb.w;
    } else {
        for (int i = base; i < e; ++i) {
            int d = dst[i];
            int p = atomicAdd(&g_cnt[d], 1);
            if (p < CAP) g_slot[(size_t)d * CAP + p] = src[i];
        }
    }
}

// ---------------- wmma GEMM: hs = half( rsqrt(cnt+1)[row] * (X[n,K] @ W[K,64]) ) ----------------
#define GEMM_SMEM 53248
__global__ void k_gemm_f16(const float* __restrict__ X, const float* __restrict__ W,
                           __half* __restrict__ Y, int n, int K) {
    extern __shared__ __align__(16) unsigned char smbuf[];
    __half (*sA)[136]  = (__half(*)[136])smbuf;                 // 34816 B
    __half (*sB)[72]   = (__half(*)[72])(smbuf + 34816);        // 18432 B
    float  (*sOut)[68] = (float(*)[68])smbuf;                   // aliases sA after compute

    const int tid = threadIdx.x;
    const int wid = tid >> 5;
    const int wr = wid >> 1;
    const int wc = wid & 1;
    const int rowBase = blockIdx.x * 128;
    const int kq = K >> 2;

    for (int i = tid; i < (128 * K) >> 2; i += 256) {
        int r = i / kq, q = i % kq;
        int row = rowBase + r;
        float4 v = make_float4(0.f, 0.f, 0.f, 0.f);
        if (row < n)
            v = *(const float4*)(X + (size_t)row * K + (q << 2));
        *(__half2*)&sA[r][(q << 2)]     = __floats2half2_rn(v.x, v.y);
        *(__half2*)&sA[r][(q << 2) + 2] = __floats2half2_rn(v.z, v.w);
    }
    for (int i = tid; i < K * 16; i += 256) {
        int r = i >> 4, q = i & 15;
        float4 v = *(const float4*)(W + (size_t)r * 64 + (q << 2));
        *(__half2*)&sB[r][(q << 2)]     = __floats2half2_rn(v.x, v.y);
        *(__half2*)&sB[r][(q << 2) + 2] = __floats2half2_rn(v.z, v.w);
    }
    __syncthreads();

    wmma::fragment<wmma::accumulator, 16, 16, 16, float> acc[2][2];
#pragma unroll
    for (int i = 0; i < 2; ++i)
#pragma unroll
        for (int j = 0; j < 2; ++j) wmma::fill_fragment(acc[i][j], 0.0f);

#pragma unroll
    for (int kk = 0; kk < 128; kk += 16) {
        if (kk >= K) break;
        wmma::fragment<wmma::matrix_a, 16, 16, 16, __half, wmma::row_major> a0, a1;
        wmma::fragment<wmma::matrix_b, 16, 16, 16, __half, wmma::row_major> b0, b1;
        wmma::load_matrix_sync(a0, &sA[wr * 32][kk], 136);
        wmma::load_matrix_sync(a1, &sA[wr * 32 + 16][kk], 136);
        wmma::load_matrix_sync(b0, &sB[kk][wc * 32], 72);
        wmma::load_matrix_sync(b1, &sB[kk][wc * 32 + 16], 72);
        wmma::mma_sync(acc[0][0], a0, b0, acc[0][0]);
        wmma::mma_sync(acc[0][1], a0, b1, acc[0][1]);
        wmma::mma_sync(acc[1][0], a1, b0, acc[1][0]);
        wmma::mma_sync(acc[1][1], a1, b1, acc[1][1]);
    }
    __syncthreads();

#pragma unroll
    for (int i = 0; i < 2; ++i)
#pragma unroll
        for (int j = 0; j < 2; ++j)
            wmma::store_matrix_sync(&sOut[wr * 32 + i * 16][wc * 32 + j * 16],
                                    acc[i][j], 68, wmma::mem_row_major);
    __syncthreads();

    // epilogue: scale by rsqrt(cnt[row]+1), fp32 -> fp16 store; 2 threads per row
    {
        int r = tid >> 1;
        int cb = (tid & 1) << 5;
        int row = rowBase + r;
        if (row < n) {
            float s = rsqrtf((float)g_cnt[row] + 1.0f);
#pragma unroll
            for (int jj = 0; jj < 4; ++jj) {
                float4 v0 = *(float4*)&sOut[r][cb + (jj << 3)];
                float4 v1 = *(float4*)&sOut[r][cb + (jj << 3) + 4];
                __half2 h[4];
                h[0] = __floats2half2_rn(v0.x * s, v0.y * s);
                h[1] = __floats2half2_rn(v0.z * s, v0.w * s);
                h[2] = __floats2half2_rn(v1.x * s, v1.y * s);
                h[3] = __floats2half2_rn(v1.z * s, v1.w * s);
                *(uint4*)(Y + (size_t)row * 64 + cb + (jj << 3)) = *(uint4*)h;
            }
        }
    }
}

// ---------------- aggregation core (exact R7 shape, fp16 messages) ----------------
// warp layout: q = lane>>3 (source slot within 4-group), r = lane&7 (channel octet).
__device__ __forceinline__ void acc_row8(float acc[8], uint4 hv) {
    __half2* h2 = (__half2*)&hv;
#pragma unroll
    for (int k = 0; k < 4; ++k) {
        float2 f = __half22float2(h2[k]);
        acc[2 * k]     += f.x;
        acc[2 * k + 1] += f.y;
    }
}

// returns deg; acc holds cross-quarter-reduced sums afterwards
__device__ __forceinline__ int agg_core(const __half* __restrict__ hs,
                                        int w, int q, int r,
                                        float acc[8]) {
#pragma unroll
    for (int k = 0; k < 8; ++k) acc[k] = 0.f;

    const __half* base = hs + (r << 3);
    if (q == 0)   // self term, counted once
        acc_row8(acc, *(const uint4*)(base + (size_t)w * 64));

    const int deg = g_cnt[w];
    const int* slotrow = g_slot + (size_t)w * CAP;
    for (int t = 0; t < deg; t += 4) {
        int idx = t + q;
        if (idx < deg) {
            int s = slotrow[idx];
            acc_row8(acc, *(const uint4*)(base + (size_t)s * 64));
        }
    }
#pragma unroll
    for (int k = 0; k < 8; ++k) {
        acc[k] += __shfl_xor_sync(0xffffffffu, acc[k], 8);
        acc[k] += __shfl_xor_sync(0xffffffffu, acc[k], 16);
    }
    return deg;
}

// ---------------- layer 1: a[d] = relu(dinv[d]*(hs[d]+sum hs[s]) + b1) ----------------
__global__ void k_agg1(const __half* __restrict__ hs, float* __restrict__ a,
                       const float* __restrict__ b1, int n) {
    int w = (blockIdx.x * blockDim.x + threadIdx.x) >> 5;
    if (w >= n) return;
    int lane = threadIdx.x & 31;
    int q = lane >> 3, r = lane & 7;

    float acc[8];
    int deg = agg_core(hs, w, q, r, acc);

    if (q == 0) {
        float dvw = rsqrtf((float)deg + 1.0f);
        float4 b0 = *(const float4*)(b1 + (r << 3));
        float4 b1v = *(const float4*)(b1 + (r << 3) + 4);
        float4 o0, o1;
        o0.x = fmaxf(acc[0] * dvw + b0.x, 0.f);
        o0.y = fmaxf(acc[1] * dvw + b0.y, 0.f);
        o0.z = fmaxf(acc[2] * dvw + b0.z, 0.f);
        o0.w = fmaxf(acc[3] * dvw + b0.w, 0.f);
        o1.x = fmaxf(acc[4] * dvw + b1v.x, 0.f);
        o1.y = fmaxf(acc[5] * dvw + b1v.y, 0.f);
        o1.z = fmaxf(acc[6] * dvw + b1v.z, 0.f);
        o1.w = fmaxf(acc[7] * dvw + b1v.w, 0.f);
        *(float4*)(a + (size_t)w * 64 + (r << 3))     = o0;
        *(float4*)(a + (size_t)w * 64 + (r << 3) + 4) = o1;
    }
}

// ---------------- layer 2 + classifier; also re-zeroes g_cnt ----------------
__global__ void k_agg2(const __half* __restrict__ hs,
                       const float* __restrict__ b2, const float* __restrict__ Wc,
                       const float* __restrict__ bc, float* __restrict__ logits, int n) {
    int w = (blockIdx.x * blockDim.x + threadIdx.x) >> 5;
    if (w >= n) return;
    int lane = threadIdx.x & 31;
    int q = lane >> 3, r = lane & 7;

    float acc[8];
    int deg = agg_core(hs, w, q, r, acc);

    float dvw = rsqrtf((float)deg + 1.0f);
    float4 b0 = *(const float4*)(b2 + (r << 3));
    float4 b1v = *(const float4*)(b2 + (r << 3) + 4);
    float4 wc0 = *(const float4*)(Wc + (r << 3));
    float4 wc1 = *(const float4*)(Wc + (r << 3) + 4);
    float sum =
        fmaxf(acc[0] * dvw + b0.x, 0.f) * wc0.x +
        fmaxf(acc[1] * dvw + b0.y, 0.f) * wc0.y +
        fmaxf(acc[2] * dvw + b0.z, 0.f) * wc0.z +
        fmaxf(acc[3] * dvw + b0.w, 0.f) * wc0.w +
        fmaxf(acc[4] * dvw + b1v.x, 0.f) * wc1.x +
        fmaxf(acc[5] * dvw + b1v.y, 0.f) * wc1.y +
        fmaxf(acc[6] * dvw + b1v.z, 0.f) * wc1.z +
        fmaxf(acc[7] * dvw + b1v.w, 0.f) * wc1.w;
    sum += __shfl_xor_sync(0xffffffffu, sum, 1);
    sum += __shfl_xor_sync(0xffffffffu, sum, 2);
    sum += __shfl_xor_sync(0xffffffffu, sum, 4);
    if (lane == 0) {
        logits[w] = sum + bc[0];
        g_cnt[w] = 0;          // ready for next call (replay determinism)
    }
}

// ---------------- launcher ----------------
extern "C" void kernel_launch(void* const* d_in, const int* in_sizes, int n_in,
                              void* d_out, int out_size) {
    const float* x  = (const float*)d_in[0];
    const int*   ei = (const int*)d_in[1];   // int32 (JAX x64 disabled)
    const float* W1 = (const float*)d_in[2];
    const float* b1 = (const float*)d_in[3];
    const float* W2 = (const float*)d_in[4];
    const float* b2 = (const float*)d_in[5];
    const float* Wc = (const float*)d_in[6];
    const float* bc = (const float*)d_in[7];
    float* logits = (float*)d_out;

    const int n = in_sizes[0] / 128;
    const int e = in_sizes[1] / 2;
    const int* src = ei;
    const int* dst = ei + e;

    __half* p_hs;
    float*  p_a;
    cudaGetSymbolAddress((void**)&p_hs, g_hs);
    cudaGetSymbolAddress((void**)&p_a,  g_a);

    static bool attr_done = false;
    if (!attr_done) {
        cudaFuncSetAttribute(k_gemm_f16, cudaFuncAttributeMaxDynamicSharedMemorySize, GEMM_SMEM);
        attr_done = true;
    }

    const int T = 256;

    // 1: bucket fill (count + insert, MLP=8)
    k_fill<<<((e >> 3) + T - 1) / T, T>>>(src, dst, e);
    // 2: layer-1 GEMM (dinv inline from cnt)
    k_gemm_f16<<<(n + 127) / 128, T, GEMM_SMEM>>>(x, W1, p_hs, n, 128);
    // 3: layer-1 aggregation
    k_agg1<<<(n * 32 + T - 1) / T, T>>>(p_hs, p_a, b1, n);
    // 4: layer-2 GEMM (profiled launch — first look at gemm2)
    k_gemm_f16<<<(n + 127) / 128, T, GEMM_SMEM>>>(p_a, W2, p_hs, n, 64);
    // 5: layer-2 aggregation + classifier
    k_agg2<<<(n * 32 + T - 1) / T, T>>>(p_hs, b2, Wc, bc, logits, n);
}